// round 2
// baseline (speedup 1.0000x reference)
#include <cuda_runtime.h>

typedef unsigned long long ull;

#define NPTS 100
#define T64  64
#define HID  4096

// ---------------- scratch (no allocations allowed) ----------------
__device__ float g_ect[256 * 4096];
__device__ float g_h1 [256 * 4096];
__device__ float g_h2 [256 * 4096];
__device__ float g_pa [4 * 256 * 4096];   // split-K partials, big GEMMs
__device__ float g_w3p[4096 * 256];       // W3 padded 200->256
__device__ float g_p3 [16 * 256 * 256];   // split-K partials, GEMM3
__device__ float g_pts[256 * 200];

// ---------------- f32x2 helpers ----------------
__device__ __forceinline__ ull f2dup(float a) {
    ull r; asm("mov.b64 %0,{%1,%1};" : "=l"(r) : "f"(a)); return r;
}
__device__ __forceinline__ ull f2fma(ull a, ull b, ull c) {
    ull d; asm("fma.rn.f32x2 %0,%1,%2,%3;" : "=l"(d) : "l"(a), "l"(b), "l"(c)); return d;
}
__device__ __forceinline__ float2 f2un(ull v) {
    float lo, hi; asm("mov.b64 {%0,%1},%2;" : "=f"(lo), "=f"(hi) : "l"(v));
    return make_float2(lo, hi);
}
__device__ __forceinline__ float sig_apx(float a) {
    float r; asm("tanh.approx.f32 %0,%1;" : "=f"(r) : "f"(a * 0.5f));
    return fmaf(0.5f, r, 0.5f);
}

// ---------------- ECT layer ----------------
// One block per graph, 128 threads: t = tid&63 (direction), half = tid>>6.
// sigmoid(500*(lin[k]-nh)) transitions within one bin (500*step = 15.87):
// evaluate k in {floor(u), floor(u)+1} exactly; bins >= floor(u)+2 counted as 1
// via suffix histogram + prefix scan; bins below dropped (sigma <= 1.3e-7).
__global__ void __launch_bounds__(128) ect_kernel(const float* __restrict__ pts,
                                                  const float* __restrict__ V,
                                                  const float* __restrict__ lin,
                                                  float* __restrict__ out)
{
    __shared__ float xs[2 * NPTS];
    __shared__ float Vs[2 * T64];
    __shared__ float lins[T64];
    __shared__ float e2[2][T64 * T64];            // 32 KB
    __shared__ unsigned char cnt2[2][T64 * T64];  // 8 KB
    __shared__ float red[128];

    const int g = blockIdx.x, tid = threadIdx.x;
    if (tid < T64) lins[tid] = lin[tid];
    Vs[tid] = V[tid];
    if (tid < NPTS) {
        float2 p = reinterpret_cast<const float2*>(pts)[g * NPTS + tid];
        xs[2 * tid] = p.x; xs[2 * tid + 1] = p.y;
    }
    for (int i = tid; i < 2 * T64 * T64; i += 128) (&e2[0][0])[i] = 0.0f;
    int* ci = reinterpret_cast<int*>(&cnt2[0][0]);
    for (int i = tid; i < (2 * T64 * T64) / 4; i += 128) ci[i] = 0;
    __syncthreads();

    const int t = tid & 63, half = tid >> 6;
    const float vx = Vs[t], vy = Vs[T64 + t];
    float* e = &e2[half][t];
    unsigned char* cc = &cnt2[half][t];
    const int nbeg = half * 50;

    for (int n = 0; n < 50; ++n) {
        const float x0 = xs[2 * (nbeg + n)], x1 = xs[2 * (nbeg + n) + 1];
        const float nh = fmaf(x0, vx, x1 * vy);
        const int kf = __float2int_rd((nh + 1.0f) * 31.5f);
        if (kf >= 0 && kf < T64)      e[kf * T64]       += sig_apx(500.0f * (lins[kf] - nh));
        if (kf + 1 >= 0 && kf + 1 < T64) e[(kf + 1) * T64] += sig_apx(500.0f * (lins[kf + 1] - nh));
        int s = kf + 2; if (s < 0) s = 0;
        if (s < T64) cc[s * T64] = (unsigned char)(cc[s * T64] + 1);
    }
    __syncthreads();

    if (tid < T64) {                 // suffix-count scan + merge halves
        float run = 0.0f;
        for (int k = 0; k < T64; ++k) {
            const int o = k * T64 + tid;
            run += (float)(cnt2[0][o] + cnt2[1][o]);
            e2[0][o] = e2[0][o] + e2[1][o] + run;
        }
    }
    __syncthreads();

    float mx = 0.0f;
    for (int i = tid; i < T64 * T64; i += 128) mx = fmaxf(mx, e2[0][i]);
    red[tid] = mx; __syncthreads();
    for (int off = 64; off > 0; off >>= 1) {
        if (tid < off) red[tid] = fmaxf(red[tid], red[tid + off]);
        __syncthreads();
    }
    const float inv = 1.0f / red[0];
    float* og = out + (long)g * (T64 * T64);
    for (int i = tid; i < T64 * T64; i += 128) og[i] = e2[0][i] * inv;
}

// ---------------- fp32 GEMM, packed f32x2 ----------------
// C_part[z] = A[256, 4096 (K-slice z)] @ B[Kslice, N]. BM=64, BN=128, BK=16,
// 128 threads, thread tile 8x8 (acc = 8x4 f32x2 along N), double buffered.
__global__ void __launch_bounds__(128) gemm_f32(const float* __restrict__ A,
                                                const float* __restrict__ B,
                                                float* __restrict__ P,
                                                int N, int ktiles)
{
    __shared__ float As[2][16][64];
    __shared__ float Bs[2][16][128];
    const int tid = threadIdx.x;
    const int m0 = blockIdx.x * 64, n0 = blockIdx.y * 128;
    const long k0 = (long)blockIdx.z * ktiles * 16;
    const float* Ag = A + (long)m0 * 4096 + k0;
    const float* Bg = B + k0 * N + n0;

    const int am = tid & 63, ak4 = tid >> 6;        // A: 2 float4 per thread
    const int bn4 = tid & 31, bk = tid >> 5;        // B: 4 float4 per thread
    const int tx = tid & 15, ty = tid >> 4;         // compute mapping

    ull acc[8][4];
    #pragma unroll
    for (int i = 0; i < 8; ++i)
        #pragma unroll
        for (int j = 0; j < 4; ++j) acc[i][j] = 0ULL;

    float4 a4[2], b4[4];
    #pragma unroll
    for (int r = 0; r < 2; ++r)
        a4[r] = *(const float4*)(Ag + (long)am * 4096 + (ak4 + 2 * r) * 4);
    #pragma unroll
    for (int r = 0; r < 4; ++r)
        b4[r] = *(const float4*)(Bg + (long)(bk + 4 * r) * N + bn4 * 4);
    #pragma unroll
    for (int r = 0; r < 2; ++r) {
        int kk = (ak4 + 2 * r) * 4;
        As[0][kk + 0][am] = a4[r].x; As[0][kk + 1][am] = a4[r].y;
        As[0][kk + 2][am] = a4[r].z; As[0][kk + 3][am] = a4[r].w;
    }
    #pragma unroll
    for (int r = 0; r < 4; ++r) *(float4*)&Bs[0][bk + 4 * r][bn4 * 4] = b4[r];
    __syncthreads();

    int buf = 0;
    for (int kt = 0; kt < ktiles; ++kt) {
        if (kt + 1 < ktiles) {
            const float* Agn = Ag + (kt + 1) * 16;
            const float* Bgn = Bg + (long)(kt + 1) * 16 * N;
            #pragma unroll
            for (int r = 0; r < 2; ++r)
                a4[r] = *(const float4*)(Agn + (long)am * 4096 + (ak4 + 2 * r) * 4);
            #pragma unroll
            for (int r = 0; r < 4; ++r)
                b4[r] = *(const float4*)(Bgn + (long)(bk + 4 * r) * N + bn4 * 4);
        }
        #pragma unroll
        for (int k = 0; k < 16; ++k) {
            float a[8]; ull bv[4];
            *(float4*)&a[0] = *(const float4*)&As[buf][k][ty * 8];
            *(float4*)&a[4] = *(const float4*)&As[buf][k][ty * 8 + 4];
            {
                ulonglong2 t0 = *(const ulonglong2*)&Bs[buf][k][tx * 8];
                ulonglong2 t1 = *(const ulonglong2*)&Bs[buf][k][tx * 8 + 4];
                bv[0] = t0.x; bv[1] = t0.y; bv[2] = t1.x; bv[3] = t1.y;
            }
            #pragma unroll
            for (int i = 0; i < 8; ++i) {
                ull av = f2dup(a[i]);
                #pragma unroll
                for (int j = 0; j < 4; ++j) acc[i][j] = f2fma(av, bv[j], acc[i][j]);
            }
        }
        if (kt + 1 < ktiles) {
            int nb = buf ^ 1;
            #pragma unroll
            for (int r = 0; r < 2; ++r) {
                int kk = (ak4 + 2 * r) * 4;
                As[nb][kk + 0][am] = a4[r].x; As[nb][kk + 1][am] = a4[r].y;
                As[nb][kk + 2][am] = a4[r].z; As[nb][kk + 3][am] = a4[r].w;
            }
            #pragma unroll
            for (int r = 0; r < 4; ++r) *(float4*)&Bs[nb][bk + 4 * r][bn4 * 4] = b4[r];
            __syncthreads();
            buf = nb;
        }
    }

    float* Pp = P + ((long)blockIdx.z * 256 + m0) * N + n0;
    #pragma unroll
    for (int i = 0; i < 8; ++i)
        #pragma unroll
        for (int j = 0; j < 4; ++j) {
            float2 v = f2un(acc[i][j]);
            *(float2*)&Pp[(long)(ty * 8 + i) * N + tx * 8 + j * 2] = v;
        }
}

// ---------------- epilogues / small kernels ----------------
__global__ void reduce_tanh(const float* __restrict__ P, const float* __restrict__ bias,
                            float* __restrict__ out)
{
    const int i = blockIdx.x * 256 + threadIdx.x;       // over 256*4096
    float s = bias[i & 4095];
    #pragma unroll
    for (int z = 0; z < 4; ++z) s += P[(long)z * 1048576 + i];
    out[i] = tanhf(s);
}

__global__ void reduce_pts(const float* __restrict__ P, const float* __restrict__ b3,
                           float* __restrict__ pts, float* __restrict__ otail)
{
    const int i = blockIdx.x * 256 + threadIdx.x;       // over 256*256
    const int m = i >> 8, n = i & 255;
    if (n >= 200) return;
    float s = b3[n];
    #pragma unroll
    for (int z = 0; z < 16; ++z) s += P[z * 65536 + i];
    pts[m * 200 + n] = s;
    otail[m * 200 + n] = s;
}

__global__ void prep_w3(const float* __restrict__ W3, float* __restrict__ W3p)
{
    const int i = blockIdx.x * 256 + threadIdx.x;       // over 4096*256
    const int k = i >> 8, n = i & 255;
    W3p[i] = (n < 200) ? W3[k * 200 + n] : 0.0f;
}

// ---------------- launch ----------------
extern "C" void kernel_launch(void* const* d_in, const int* in_sizes, int n_in,
                              void* d_out, int out_size)
{
    const float* x   = (const float*)d_in[0];
    const float* V   = (const float*)d_in[2];
    const float* lin = (const float*)d_in[3];
    const float* W1  = (const float*)d_in[4];
    const float* b1  = (const float*)d_in[5];
    const float* W2  = (const float*)d_in[6];
    const float* b2  = (const float*)d_in[7];
    const float* W3  = (const float*)d_in[8];
    const float* b3  = (const float*)d_in[9];
    float* out = (float*)d_out;

    float *ect, *h1, *h2, *pa, *w3p, *p3, *pts;
    cudaGetSymbolAddress((void**)&ect, g_ect);
    cudaGetSymbolAddress((void**)&h1,  g_h1);
    cudaGetSymbolAddress((void**)&h2,  g_h2);
    cudaGetSymbolAddress((void**)&pa,  g_pa);
    cudaGetSymbolAddress((void**)&w3p, g_w3p);
    cudaGetSymbolAddress((void**)&p3,  g_p3);
    cudaGetSymbolAddress((void**)&pts, g_pts);

    ect_kernel<<<256, 128>>>(x, V, lin, ect);
    prep_w3<<<4096, 256>>>(W3, w3p);

    gemm_f32<<<dim3(4, 32, 4), 128>>>(ect, W1, pa, 4096, 64);
    reduce_tanh<<<4096, 256>>>(pa, b1, h1);

    gemm_f32<<<dim3(4, 32, 4), 128>>>(h1, W2, pa, 4096, 64);
    reduce_tanh<<<4096, 256>>>(pa, b2, h2);

    gemm_f32<<<dim3(4, 2, 16), 128>>>(h2, w3p, p3, 256, 16);
    reduce_pts<<<256, 256>>>(p3, b3, pts, out + 256 * 64 * 64);

    ect_kernel<<<256, 128>>>(pts, V, lin, out);
}

// round 4
// speedup vs baseline: 1.8010x; 1.8010x over previous
#include <cuda_runtime.h>
#include <cuda_bf16.h>
#include <cstdint>

typedef unsigned long long ull;

#define NPTS 100
#define T64  64

// ---------------- scratch ----------------
__device__ __nv_bfloat16 g_Ah [256 * 4096], g_Al [256 * 4096];
__device__ __nv_bfloat16 g_Ah2[256 * 4096], g_Al2[256 * 4096];
__device__ __nv_bfloat16 g_W1h[4096u * 4096u], g_W1l[4096u * 4096u];
__device__ __nv_bfloat16 g_W2h[4096u * 4096u], g_W2l[4096u * 4096u];
__device__ float g_h2 [256 * 4096];
__device__ float g_w3p[4096 * 256];
__device__ float g_p3 [16 * 256 * 256];
__device__ float g_pts[256 * 200];

// ---------------- helpers ----------------
__device__ __forceinline__ ull f2dup(float a) {
    ull r; asm("mov.b64 %0,{%1,%1};" : "=l"(r) : "f"(a)); return r;
}
__device__ __forceinline__ ull f2fma(ull a, ull b, ull c) {
    ull d; asm("fma.rn.f32x2 %0,%1,%2,%3;" : "=l"(d) : "l"(a), "l"(b), "l"(c)); return d;
}
__device__ __forceinline__ float2 f2un(ull v) {
    float lo, hi; asm("mov.b64 {%0,%1},%2;" : "=f"(lo), "=f"(hi) : "l"(v));
    return make_float2(lo, hi);
}
__device__ __forceinline__ float sig_apx(float a) {
    float r; asm("tanh.approx.f32 %0,%1;" : "=f"(r) : "f"(a * 0.5f));
    return fmaf(0.5f, r, 0.5f);
}
__device__ __forceinline__ void split_bf16(float v, __nv_bfloat16& h, __nv_bfloat16& l) {
    h = __float2bfloat16(v);
    l = __float2bfloat16(v - __bfloat162float(h));
}
__device__ __forceinline__ void mma16816(float* c, const uint32_t* a, const uint32_t* b) {
    asm volatile("mma.sync.aligned.m16n8k16.row.col.f32.bf16.bf16.f32 "
        "{%0,%1,%2,%3}, {%4,%5,%6,%7}, {%8,%9}, {%0,%1,%2,%3};"
        : "+f"(c[0]), "+f"(c[1]), "+f"(c[2]), "+f"(c[3])
        : "r"(a[0]), "r"(a[1]), "r"(a[2]), "r"(a[3]), "r"(b[0]), "r"(b[1]));
}
__device__ __forceinline__ uint32_t lds32(const char* p) {
    return *reinterpret_cast<const uint32_t*>(p);
}

// ---------------- ECT layer ----------------
__global__ void __launch_bounds__(128) ect_kernel(const float* __restrict__ pts,
                                                  const float* __restrict__ V,
                                                  const float* __restrict__ lin,
                                                  float* __restrict__ outf,
                                                  __nv_bfloat16* __restrict__ outh,
                                                  __nv_bfloat16* __restrict__ outl)
{
    __shared__ float xs[2 * NPTS];
    __shared__ float Vs[2 * T64];
    __shared__ float lins[T64];
    __shared__ float e2[2][T64 * T64];
    __shared__ unsigned char cnt2[2][T64 * T64];
    __shared__ float red[128];

    const int g = blockIdx.x, tid = threadIdx.x;
    if (tid < T64) lins[tid] = lin[tid];
    Vs[tid] = V[tid];
    if (tid < NPTS) {
        float2 p = reinterpret_cast<const float2*>(pts)[g * NPTS + tid];
        xs[2 * tid] = p.x; xs[2 * tid + 1] = p.y;
    }
    for (int i = tid; i < 2 * T64 * T64; i += 128) (&e2[0][0])[i] = 0.0f;
    int* ci = reinterpret_cast<int*>(&cnt2[0][0]);
    for (int i = tid; i < (2 * T64 * T64) / 4; i += 128) ci[i] = 0;
    __syncthreads();

    const int t = tid & 63, half = tid >> 6;
    const float vx = Vs[t], vy = Vs[T64 + t];
    float* e = &e2[half][t];
    unsigned char* cc = &cnt2[half][t];
    const int nbeg = half * 50;

    for (int n = 0; n < 50; ++n) {
        const float x0 = xs[2 * (nbeg + n)], x1 = xs[2 * (nbeg + n) + 1];
        const float nh = fmaf(x0, vx, x1 * vy);
        const int kf = __float2int_rd((nh + 1.0f) * 31.5f);
        if (kf >= 0 && kf < T64)         e[kf * T64]       += sig_apx(500.0f * (lins[kf] - nh));
        if (kf + 1 >= 0 && kf + 1 < T64) e[(kf + 1) * T64] += sig_apx(500.0f * (lins[kf + 1] - nh));
        int s = kf + 2; if (s < 0) s = 0;
        if (s < T64) cc[s * T64] = (unsigned char)(cc[s * T64] + 1);
    }
    __syncthreads();

    if (tid < T64) {
        float run = 0.0f;
        for (int k = 0; k < T64; ++k) {
            const int o = k * T64 + tid;
            run += (float)(cnt2[0][o] + cnt2[1][o]);
            e2[0][o] = e2[0][o] + e2[1][o] + run;
        }
    }
    __syncthreads();

    float mx = 0.0f;
    for (int i = tid; i < T64 * T64; i += 128) mx = fmaxf(mx, e2[0][i]);
    red[tid] = mx; __syncthreads();
    for (int off = 64; off > 0; off >>= 1) {
        if (tid < off) red[tid] = fmaxf(red[tid], red[tid + off]);
        __syncthreads();
    }
    const float inv = 1.0f / red[0];
    for (int i = tid; i < T64 * T64; i += 128) {
        float v = e2[0][i] * inv;
        if (outf) outf[(long)g * 4096 + i] = v;
        if (outh) {
            __nv_bfloat16 h, l; split_bf16(v, h, l);
            outh[(long)g * 4096 + i] = h;
            outl[(long)g * 4096 + i] = l;
        }
    }
}

// ---------------- W transpose + bf16 hi/lo split ----------------
__global__ void __launch_bounds__(256) transpose_w(const float* __restrict__ W,
                                                   __nv_bfloat16* __restrict__ Th,
                                                   __nv_bfloat16* __restrict__ Tl)
{
    __shared__ float tile[32][33];
    const int k0 = blockIdx.x * 32, n0 = blockIdx.y * 32;
    const int tid = threadIdx.x;
    #pragma unroll
    for (int i = 0; i < 4; ++i) {
        int e = i * 256 + tid, kk = e >> 5, nn = e & 31;
        tile[kk][nn] = W[(long)(k0 + kk) * 4096 + n0 + nn];
    }
    __syncthreads();
    #pragma unroll
    for (int i = 0; i < 2; ++i) {
        int e = i * 256 + tid, nn = e >> 4, k2 = e & 15;
        float f0 = tile[k2 * 2][nn], f1 = tile[k2 * 2 + 1][nn];
        __nv_bfloat16 h0, l0, h1, l1;
        split_bf16(f0, h0, l0); split_bf16(f1, h1, l1);
        long o = (long)(n0 + nn) * 4096 + k0 + k2 * 2;
        *reinterpret_cast<__nv_bfloat162*>(Th + o) = __halves2bfloat162(h0, h1);
        *reinterpret_cast<__nv_bfloat162*>(Tl + o) = __halves2bfloat162(l0, l1);
    }
}

// ---------------- HMMA GEMM: C = tanh(Ah(Bh+Bl) + AlBh + bias) ----------------
// A[256,4096] bf16 rows; B = W^T [n][k] bf16 rows. CTA 64x128, BK=64, 8 warps
// (2x4), warp tile 32x32, SW128 smem, double buffered. Fused epilogue.
#define STG 49152
#define GMEM_SM (2 * STG)
#define SW(b) ((b) ^ (((b) >> 3) & 0x70))

__global__ void __launch_bounds__(256, 1) gemm_mma(const __nv_bfloat16* __restrict__ Ah,
                                                   const __nv_bfloat16* __restrict__ Al,
                                                   const __nv_bfloat16* __restrict__ Bh,
                                                   const __nv_bfloat16* __restrict__ Bl,
                                                   const float* __restrict__ bias,
                                                   float* __restrict__ outF,
                                                   __nv_bfloat16* __restrict__ oH,
                                                   __nv_bfloat16* __restrict__ oL)
{
    extern __shared__ __align__(16) char dsm[];
    const int tid = threadIdx.x;
    const int lane = tid & 31, wid = tid >> 5;
    const int wm = wid >> 2, wn = wid & 3;          // warp grid 2x4
    const int laneR = lane >> 2;                    // 0..7
    const int laneK4 = (lane & 3) * 4;              // byte offset in k
    const int m0 = blockIdx.x * 64, n0 = blockIdx.y * 128;

    float acc[2][4][4];
    #pragma unroll
    for (int a = 0; a < 2; ++a)
        #pragma unroll
        for (int b = 0; b < 4; ++b)
            #pragma unroll
            for (int c = 0; c < 4; ++c) acc[a][b][c] = 0.0f;

    uint4 rah[2], ral[2], rbh[4], rbl[4];

    // prologue loads for kt=0
    #pragma unroll
    for (int i = 0; i < 2; ++i) {
        int idx = tid + 256 * i, row = idx >> 3, kq = idx & 7;
        long off = (long)(m0 + row) * 4096 + kq * 8;
        rah[i] = *(const uint4*)(Ah + off);
        ral[i] = *(const uint4*)(Al + off);
    }
    #pragma unroll
    for (int i = 0; i < 4; ++i) {
        int idx = tid + 256 * i, row = idx >> 3, kq = idx & 7;
        long off = (long)(n0 + row) * 4096 + kq * 8;
        rbh[i] = *(const uint4*)(Bh + off);
        rbl[i] = *(const uint4*)(Bl + off);
    }
    // store stage 0
    #pragma unroll
    for (int i = 0; i < 2; ++i) {
        int idx = tid + 256 * i, row = idx >> 3, kq = idx & 7;
        uint32_t sw = row * 128 + ((kq * 16) ^ ((row & 7) << 4));
        *(uint4*)(dsm + sw)        = rah[i];
        *(uint4*)(dsm + 8192 + sw) = ral[i];
    }
    #pragma unroll
    for (int i = 0; i < 4; ++i) {
        int idx = tid + 256 * i, row = idx >> 3, kq = idx & 7;
        uint32_t sw = row * 128 + ((kq * 16) ^ ((row & 7) << 4));
        *(uint4*)(dsm + 16384 + sw) = rbh[i];
        *(uint4*)(dsm + 32768 + sw) = rbl[i];
    }
    __syncthreads();

    const int swz = laneR << 4;

    for (int kt = 0; kt < 64; ++kt) {
        if (kt + 1 < 64) {
            #pragma unroll
            for (int i = 0; i < 2; ++i) {
                int idx = tid + 256 * i, row = idx >> 3, kq = idx & 7;
                long off = (long)(m0 + row) * 4096 + (kt + 1) * 64 + kq * 8;
                rah[i] = *(const uint4*)(Ah + off);
                ral[i] = *(const uint4*)(Al + off);
            }
            #pragma unroll
            for (int i = 0; i < 4; ++i) {
                int idx = tid + 256 * i, row = idx >> 3, kq = idx & 7;
                long off = (long)(n0 + row) * 4096 + (kt + 1) * 64 + kq * 8;
                rbh[i] = *(const uint4*)(Bh + off);
                rbl[i] = *(const uint4*)(Bl + off);
            }
        }

        const char* st = dsm + (kt & 1) * STG;
        #pragma unroll
        for (int ks = 0; ks < 4; ++ks) {
            const int kb = ks * 32 + laneK4;
            const int k0x = kb ^ swz, k1x = (kb + 16) ^ swz;
            uint32_t fAh[2][4], fAl[2][4], fBh[4][2], fBl[4][2];
            #pragma unroll
            for (int mt = 0; mt < 2; ++mt) {
                const int r0 = (wm * 32 + mt * 16 + laneR) * 128;
                const int r1 = r0 + 8 * 128;
                fAh[mt][0] = lds32(st + r0 + k0x);
                fAh[mt][1] = lds32(st + r1 + k0x);
                fAh[mt][2] = lds32(st + r0 + k1x);
                fAh[mt][3] = lds32(st + r1 + k1x);
                fAl[mt][0] = lds32(st + 8192 + r0 + k0x);
                fAl[mt][1] = lds32(st + 8192 + r1 + k0x);
                fAl[mt][2] = lds32(st + 8192 + r0 + k1x);
                fAl[mt][3] = lds32(st + 8192 + r1 + k1x);
            }
            #pragma unroll
            for (int nt = 0; nt < 4; ++nt) {
                const int rb = (wn * 32 + nt * 8 + laneR) * 128;
                fBh[nt][0] = lds32(st + 16384 + rb + k0x);
                fBh[nt][1] = lds32(st + 16384 + rb + k1x);
                fBl[nt][0] = lds32(st + 32768 + rb + k0x);
                fBl[nt][1] = lds32(st + 32768 + rb + k1x);
            }
            #pragma unroll
            for (int mt = 0; mt < 2; ++mt)
                #pragma unroll
                for (int nt = 0; nt < 4; ++nt) {
                    mma16816(acc[mt][nt], fAh[mt], fBh[nt]);
                    mma16816(acc[mt][nt], fAh[mt], fBl[nt]);
                    mma16816(acc[mt][nt], fAl[mt], fBh[nt]);
                }
        }

        if (kt + 1 < 64) {
            char* nx = dsm + ((kt + 1) & 1) * STG;
            #pragma unroll
            for (int i = 0; i < 2; ++i) {
                int idx = tid + 256 * i, row = idx >> 3, kq = idx & 7;
                uint32_t sw = row * 128 + ((kq * 16) ^ ((row & 7) << 4));
                *(uint4*)(nx + sw)        = rah[i];
                *(uint4*)(nx + 8192 + sw) = ral[i];
            }
            #pragma unroll
            for (int i = 0; i < 4; ++i) {
                int idx = tid + 256 * i, row = idx >> 3, kq = idx & 7;
                uint32_t sw = row * 128 + ((kq * 16) ^ ((row & 7) << 4));
                *(uint4*)(nx + 16384 + sw) = rbh[i];
                *(uint4*)(nx + 32768 + sw) = rbl[i];
            }
            __syncthreads();
        }
    }

    // fused epilogue: bias + tanh + outputs
    #pragma unroll
    for (int mt = 0; mt < 2; ++mt)
        #pragma unroll
        for (int nt = 0; nt < 4; ++nt) {
            const int r0 = m0 + wm * 32 + mt * 16 + laneR;
            const int nc = n0 + wn * 32 + nt * 8 + 2 * (lane & 3);
            const float b0 = bias[nc], b1 = bias[nc + 1];
            float v00 = tanhf(acc[mt][nt][0] + b0);
            float v01 = tanhf(acc[mt][nt][1] + b1);
            float v10 = tanhf(acc[mt][nt][2] + b0);
            float v11 = tanhf(acc[mt][nt][3] + b1);
            if (outF) {
                *(float2*)(outF + (long)r0 * 4096 + nc)       = make_float2(v00, v01);
                *(float2*)(outF + (long)(r0 + 8) * 4096 + nc) = make_float2(v10, v11);
            }
            if (oH) {
                __nv_bfloat16 h00, l00, h01, l01, h10, l10, h11, l11;
                split_bf16(v00, h00, l00); split_bf16(v01, h01, l01);
                split_bf16(v10, h10, l10); split_bf16(v11, h11, l11);
                *(__nv_bfloat162*)(oH + (long)r0 * 4096 + nc)       = __halves2bfloat162(h00, h01);
                *(__nv_bfloat162*)(oH + (long)(r0 + 8) * 4096 + nc) = __halves2bfloat162(h10, h11);
                *(__nv_bfloat162*)(oL + (long)r0 * 4096 + nc)       = __halves2bfloat162(l00, l01);
                *(__nv_bfloat162*)(oL + (long)(r0 + 8) * 4096 + nc) = __halves2bfloat162(l10, l11);
            }
        }
}

// ---------------- fp32 GEMM (packed f32x2) for GEMM3 ----------------
__global__ void __launch_bounds__(128) gemm_f32(const float* __restrict__ A,
                                                const float* __restrict__ B,
                                                float* __restrict__ P,
                                                int N, int ktiles)
{
    __shared__ float As[2][16][64];
    __shared__ float Bs[2][16][128];
    const int tid = threadIdx.x;
    const int m0 = blockIdx.x * 64, n0 = blockIdx.y * 128;
    const long k0 = (long)blockIdx.z * ktiles * 16;
    const float* Ag = A + (long)m0 * 4096 + k0;
    const float* Bg = B + k0 * N + n0;

    const int am = tid & 63, ak4 = tid >> 6;
    const int bn4 = tid & 31, bk = tid >> 5;
    const int tx = tid & 15, ty = tid >> 4;

    ull acc[8][4];
    #pragma unroll
    for (int i = 0; i < 8; ++i)
        #pragma unroll
        for (int j = 0; j < 4; ++j) acc[i][j] = 0ULL;

    float4 a4[2], b4[4];
    #pragma unroll
    for (int r = 0; r < 2; ++r)
        a4[r] = *(const float4*)(Ag + (long)am * 4096 + (ak4 + 2 * r) * 4);
    #pragma unroll
    for (int r = 0; r < 4; ++r)
        b4[r] = *(const float4*)(Bg + (long)(bk + 4 * r) * N + bn4 * 4);
    #pragma unroll
    for (int r = 0; r < 2; ++r) {
        int kk = (ak4 + 2 * r) * 4;
        As[0][kk + 0][am] = a4[r].x; As[0][kk + 1][am] = a4[r].y;
        As[0][kk + 2][am] = a4[r].z; As[0][kk + 3][am] = a4[r].w;
    }
    #pragma unroll
    for (int r = 0; r < 4; ++r) *(float4*)&Bs[0][bk + 4 * r][bn4 * 4] = b4[r];
    __syncthreads();

    int buf = 0;
    for (int kt = 0; kt < ktiles; ++kt) {
        if (kt + 1 < ktiles) {
            const float* Agn = Ag + (kt + 1) * 16;
            const float* Bgn = Bg + (long)(kt + 1) * 16 * N;
            #pragma unroll
            for (int r = 0; r < 2; ++r)
                a4[r] = *(const float4*)(Agn + (long)am * 4096 + (ak4 + 2 * r) * 4);
            #pragma unroll
            for (int r = 0; r < 4; ++r)
                b4[r] = *(const float4*)(Bgn + (long)(bk + 4 * r) * N + bn4 * 4);
        }
        #pragma unroll
        for (int k = 0; k < 16; ++k) {
            float a[8]; ull bv[4];
            *(float4*)&a[0] = *(const float4*)&As[buf][k][ty * 8];
            *(float4*)&a[4] = *(const float4*)&As[buf][k][ty * 8 + 4];
            {
                ulonglong2 t0 = *(const ulonglong2*)&Bs[buf][k][tx * 8];
                ulonglong2 t1 = *(const ulonglong2*)&Bs[buf][k][tx * 8 + 4];
                bv[0] = t0.x; bv[1] = t0.y; bv[2] = t1.x; bv[3] = t1.y;
            }
            #pragma unroll
            for (int i = 0; i < 8; ++i) {
                ull av = f2dup(a[i]);
                #pragma unroll
                for (int j = 0; j < 4; ++j) acc[i][j] = f2fma(av, bv[j], acc[i][j]);
            }
        }
        if (kt + 1 < ktiles) {
            int nb = buf ^ 1;
            #pragma unroll
            for (int r = 0; r < 2; ++r) {
                int kk = (ak4 + 2 * r) * 4;
                As[nb][kk + 0][am] = a4[r].x; As[nb][kk + 1][am] = a4[r].y;
                As[nb][kk + 2][am] = a4[r].z; As[nb][kk + 3][am] = a4[r].w;
            }
            #pragma unroll
            for (int r = 0; r < 4; ++r) *(float4*)&Bs[nb][bk + 4 * r][bn4 * 4] = b4[r];
            __syncthreads();
            buf = nb;
        }
    }

    float* Pp = P + ((long)blockIdx.z * 256 + m0) * N + n0;
    #pragma unroll
    for (int i = 0; i < 8; ++i)
        #pragma unroll
        for (int j = 0; j < 4; ++j) {
            float2 v = f2un(acc[i][j]);
            *(float2*)&Pp[(long)(ty * 8 + i) * N + tx * 8 + j * 2] = v;
        }
}

// ---------------- small kernels ----------------
__global__ void reduce_pts(const float* __restrict__ P, const float* __restrict__ b3,
                           float* __restrict__ pts, float* __restrict__ otail)
{
    const int i = blockIdx.x * 256 + threadIdx.x;
    const int m = i >> 8, n = i & 255;
    if (n >= 200) return;
    float s = b3[n];
    #pragma unroll
    for (int zz = 0; zz < 16; ++zz) s += P[zz * 65536 + i];
    pts[m * 200 + n] = s;
    otail[m * 200 + n] = s;
}

__global__ void prep_w3(const float* __restrict__ W3, float* __restrict__ W3p)
{
    const int i = blockIdx.x * 256 + threadIdx.x;
    const int k = i >> 8, n = i & 255;
    W3p[i] = (n < 200) ? W3[k * 200 + n] : 0.0f;
}

// ---------------- launch ----------------
extern "C" void kernel_launch(void* const* d_in, const int* in_sizes, int n_in,
                              void* d_out, int out_size)
{
    const float* x   = (const float*)d_in[0];
    const float* V   = (const float*)d_in[2];
    const float* lin = (const float*)d_in[3];
    const float* W1  = (const float*)d_in[4];
    const float* b1  = (const float*)d_in[5];
    const float* W2  = (const float*)d_in[6];
    const float* b2  = (const float*)d_in[7];
    const float* W3  = (const float*)d_in[8];
    const float* b3  = (const float*)d_in[9];
    float* out = (float*)d_out;

    __nv_bfloat16 *Ah, *Al, *Ah2, *Al2, *W1h, *W1l, *W2h, *W2l;
    float *h2, *w3p, *p3, *pts;
    cudaGetSymbolAddress((void**)&Ah,  g_Ah);
    cudaGetSymbolAddress((void**)&Al,  g_Al);
    cudaGetSymbolAddress((void**)&Ah2, g_Ah2);
    cudaGetSymbolAddress((void**)&Al2, g_Al2);
    cudaGetSymbolAddress((void**)&W1h, g_W1h);
    cudaGetSymbolAddress((void**)&W1l, g_W1l);
    cudaGetSymbolAddress((void**)&W2h, g_W2h);
    cudaGetSymbolAddress((void**)&W2l, g_W2l);
    cudaGetSymbolAddress((void**)&h2,  g_h2);
    cudaGetSymbolAddress((void**)&w3p, g_w3p);
    cudaGetSymbolAddress((void**)&p3,  g_p3);
    cudaGetSymbolAddress((void**)&pts, g_pts);

    cudaFuncSetAttribute(gemm_mma, cudaFuncAttributeMaxDynamicSharedMemorySize, GMEM_SM);

    transpose_w<<<dim3(128, 128), 256>>>(W1, W1h, W1l);
    transpose_w<<<dim3(128, 128), 256>>>(W2, W2h, W2l);
    ect_kernel<<<256, 128>>>(x, V, lin, nullptr, Ah, Al);
    prep_w3<<<4096, 256>>>(W3, w3p);

    gemm_mma<<<dim3(4, 32), 256, GMEM_SM>>>(Ah, Al, W1h, W1l, b1, nullptr, Ah2, Al2);
    gemm_mma<<<dim3(4, 32), 256, GMEM_SM>>>(Ah2, Al2, W2h, W2l, b2, h2, nullptr, nullptr);

    gemm_f32<<<dim3(4, 2, 16), 128>>>(h2, w3p, p3, 256, 16);
    reduce_pts<<<256, 256>>>(p3, b3, pts, out + 256 * 64 * 64);

    ect_kernel<<<256, 128>>>(pts, V, lin, out, nullptr, nullptr);
}

// round 5
// speedup vs baseline: 1.9730x; 1.0955x over previous
#include <cuda_runtime.h>
#include <cuda_bf16.h>
#include <cstdint>

typedef __nv_bfloat16 bf16;

// ---------------- scratch ----------------
__device__ bf16 g_Ah [256 * 4096], g_Al [256 * 4096];
__device__ bf16 g_Ah2[256 * 4096], g_Al2[256 * 4096];
__device__ bf16 g_Ah3[256 * 4096], g_Al3[256 * 4096];
__device__ bf16 g_W1h[4096u * 4096u], g_W1l[4096u * 4096u];
__device__ bf16 g_W2h[4096u * 4096u], g_W2l[4096u * 4096u];
__device__ bf16 g_W3h[256 * 4096],   g_W3l[256 * 4096];
__device__ float g_p3 [16 * 256 * 256];
__device__ float g_pts[256 * 200];

// ---------------- helpers ----------------
__device__ __forceinline__ float sig_apx(float a) {
    float r; asm("tanh.approx.f32 %0,%1;" : "=f"(r) : "f"(a * 0.5f));
    return fmaf(0.5f, r, 0.5f);
}
__device__ __forceinline__ void split_bf16(float v, bf16& h, bf16& l) {
    h = __float2bfloat16(v);
    l = __float2bfloat16(v - __bfloat162float(h));
}
__device__ __forceinline__ void mma16816(float* c, const uint32_t* a, const uint32_t* b) {
    asm volatile("mma.sync.aligned.m16n8k16.row.col.f32.bf16.bf16.f32 "
        "{%0,%1,%2,%3}, {%4,%5,%6,%7}, {%8,%9}, {%0,%1,%2,%3};"
        : "+f"(c[0]), "+f"(c[1]), "+f"(c[2]), "+f"(c[3])
        : "r"(a[0]), "r"(a[1]), "r"(a[2]), "r"(a[3]), "r"(b[0]), "r"(b[1]));
}
__device__ __forceinline__ uint32_t lds32(const char* p) {
    return *reinterpret_cast<const uint32_t*>(p);
}

// ---------------- ECT body (256 threads) ----------------
struct EctSm {
    float xs[200];
    float Vs[128];
    float lins[64];
    float e2[2][4096];
    unsigned char cnt2[2][4096];
    float red[256];
};
#define PREP_SMEM (sizeof(EctSm))

__device__ void ect_body(int g, int tid, const float* __restrict__ pts,
                         const float* __restrict__ V, const float* __restrict__ lin,
                         float* __restrict__ outf, bf16* __restrict__ outh,
                         bf16* __restrict__ outl, char* sm)
{
    EctSm& S = *reinterpret_cast<EctSm*>(sm);
    if (tid < 64)  S.lins[tid] = lin[tid];
    if (tid < 128) S.Vs[tid] = V[tid];
    if (tid < 100) {
        float2 p = reinterpret_cast<const float2*>(pts)[g * 100 + tid];
        S.xs[2 * tid] = p.x; S.xs[2 * tid + 1] = p.y;
    }
    for (int i = tid; i < 8192; i += 256) (&S.e2[0][0])[i] = 0.0f;
    for (int i = tid; i < 2048; i += 256) reinterpret_cast<int*>(S.cnt2)[i] = 0;
    __syncthreads();

    if (tid < 128) {
        const int t = tid & 63, half = tid >> 6;
        const float vx = S.Vs[t], vy = S.Vs[64 + t];
        float* e = &S.e2[half][t];
        unsigned char* cc = &S.cnt2[half][t];
        const int nbeg = half * 50;
        for (int n = 0; n < 50; ++n) {
            const float x0 = S.xs[2 * (nbeg + n)], x1 = S.xs[2 * (nbeg + n) + 1];
            const float nh = fmaf(x0, vx, x1 * vy);
            const int kf = __float2int_rd((nh + 1.0f) * 31.5f);
            if (kf >= 0 && kf < 64)         e[kf * 64]       += sig_apx(500.0f * (S.lins[kf] - nh));
            if (kf + 1 >= 0 && kf + 1 < 64) e[(kf + 1) * 64] += sig_apx(500.0f * (S.lins[kf + 1] - nh));
            int s = kf + 2; if (s < 0) s = 0;
            if (s < 64) cc[s * 64] = (unsigned char)(cc[s * 64] + 1);
        }
    }
    __syncthreads();

    if (tid < 64) {
        float run = 0.0f;
        for (int k = 0; k < 64; ++k) {
            const int o = k * 64 + tid;
            run += (float)(S.cnt2[0][o] + S.cnt2[1][o]);
            S.e2[0][o] = S.e2[0][o] + S.e2[1][o] + run;
        }
    }
    __syncthreads();

    float mx = 0.0f;
    for (int i = tid; i < 4096; i += 256) mx = fmaxf(mx, S.e2[0][i]);
    S.red[tid] = mx; __syncthreads();
    for (int off = 128; off > 0; off >>= 1) {
        if (tid < off) S.red[tid] = fmaxf(S.red[tid], S.red[tid + off]);
        __syncthreads();
    }
    const float inv = 1.0f / S.red[0];
    for (int i = tid; i < 4096; i += 256) {
        float v = S.e2[0][i] * inv;
        if (outf) outf[(long)g * 4096 + i] = v;
        if (outh) {
            bf16 h, l; split_bf16(v, h, l);
            outh[(long)g * 4096 + i] = h;
            outl[(long)g * 4096 + i] = l;
        }
    }
}

// ---------------- transpose body: W[k][n] -> T[n][k] hi/lo bf16, 64x64 tile ----------------
__device__ void transpose_body(int kt, int ntile, int tid, const float* __restrict__ W,
                               int Wn, bf16* __restrict__ Th, bf16* __restrict__ Tl, char* sm)
{
    float (*s)[65] = reinterpret_cast<float(*)[65]>(sm);
    const int k0 = kt * 64, n0 = ntile * 64;
    const int r = tid >> 4, c4 = (tid & 15) * 4;
    #pragma unroll
    for (int p = 0; p < 4; ++p) {
        const int kk = p * 16 + r;
        float4 v;
        if (Wn == 4096) {
            v = *reinterpret_cast<const float4*>(W + (long)(k0 + kk) * 4096 + n0 + c4);
        } else {   // W3: [4096][200], pad n to 256 with zeros
            float t0 = 0, t1 = 0, t2 = 0, t3 = 0;
            const long base = (long)(k0 + kk) * 200;
            if (n0 + c4 + 0 < 200) t0 = W[base + n0 + c4 + 0];
            if (n0 + c4 + 1 < 200) t1 = W[base + n0 + c4 + 1];
            if (n0 + c4 + 2 < 200) t2 = W[base + n0 + c4 + 2];
            if (n0 + c4 + 3 < 200) t3 = W[base + n0 + c4 + 3];
            v = make_float4(t0, t1, t2, t3);
        }
        s[kk][c4] = v.x; s[kk][c4 + 1] = v.y; s[kk][c4 + 2] = v.z; s[kk][c4 + 3] = v.w;
    }
    __syncthreads();
    #pragma unroll
    for (int q = 0; q < 2; ++q) {
        const int idx = tid + 256 * q;       // 512 items: n = idx>>3, kg = idx&7
        const int n = idx >> 3, kg = idx & 7;
        uint4 uh, ul;
        __nv_bfloat162* ph = reinterpret_cast<__nv_bfloat162*>(&uh);
        __nv_bfloat162* pl = reinterpret_cast<__nv_bfloat162*>(&ul);
        #pragma unroll
        for (int j = 0; j < 4; ++j) {
            bf16 h0, l0, h1, l1;
            split_bf16(s[kg * 8 + 2 * j][n],     h0, l0);
            split_bf16(s[kg * 8 + 2 * j + 1][n], h1, l1);
            ph[j] = __halves2bfloat162(h0, h1);
            pl[j] = __halves2bfloat162(l0, l1);
        }
        const long o = (long)(n0 + n) * 4096 + k0 + kg * 8;
        *reinterpret_cast<uint4*>(Th + o) = uh;
        *reinterpret_cast<uint4*>(Tl + o) = ul;
    }
}

// ---------------- fused prep: W1^T, W2^T, W3^T (padded), ect1 ----------------
__global__ void __launch_bounds__(256) prep_all(const float* __restrict__ x,
    const float* __restrict__ V, const float* __restrict__ lin,
    const float* __restrict__ W1, const float* __restrict__ W2, const float* __restrict__ W3,
    bf16* W1h, bf16* W1l, bf16* W2h, bf16* W2l, bf16* W3h, bf16* W3l,
    bf16* Ah, bf16* Al)
{
    extern __shared__ char sm[];
    int b = blockIdx.x;
    const int tid = threadIdx.x;
    if (b < 4096)       transpose_body(b & 63, b >> 6, tid, W1, 4096, W1h, W1l, sm);
    else if (b < 8192) { b -= 4096; transpose_body(b & 63, b >> 6, tid, W2, 4096, W2h, W2l, sm); }
    else if (b < 8448) { b -= 8192; transpose_body(b & 63, b >> 6, tid, W3,  200, W3h, W3l, sm); }
    else                ect_body(b - 8448, tid, x, V, lin, nullptr, Ah, Al, sm);
}

__global__ void __launch_bounds__(256) ect_final(const float* __restrict__ pts,
    const float* __restrict__ V, const float* __restrict__ lin, float* __restrict__ out)
{
    extern __shared__ char sm[];
    ect_body(blockIdx.x, threadIdx.x, pts, V, lin, out, nullptr, nullptr, sm);
}

// ---------------- HMMA GEMM, bf16 hi/lo 3-product ----------------
// CTA 64x128, BK=64, 8 warps (2x4), warp 32x32, SW128 smem, double buffered.
// TANH: K=KT*64 full, epilogue bias+tanh+split -> oH/oL (row stride 4096).
// !TANH: split-K over blockIdx.z, raw fp32 partials -> oP[z][256][256].
#define STG 49152
#define GMEM_SM (2 * STG)

template<int KT, bool TANH>
__global__ void __launch_bounds__(256, 1) gemm_mma(const bf16* __restrict__ Ah,
                                                   const bf16* __restrict__ Al,
                                                   const bf16* __restrict__ Bh,
                                                   const bf16* __restrict__ Bl,
                                                   const float* __restrict__ bias,
                                                   bf16* __restrict__ oH,
                                                   bf16* __restrict__ oL,
                                                   float* __restrict__ oP)
{
    extern __shared__ __align__(16) char dsm[];
    const int tid = threadIdx.x;
    const int lane = tid & 31, wid = tid >> 5;
    const int wm = wid >> 2, wn = wid & 3;
    const int laneR = lane >> 2;
    const int laneK4 = (lane & 3) * 4;
    const int m0 = blockIdx.x * 64, n0 = blockIdx.y * 128;
    const long kOff = TANH ? 0 : (long)blockIdx.z * (KT * 64);

    float acc[2][4][4];
    #pragma unroll
    for (int a = 0; a < 2; ++a)
        #pragma unroll
        for (int b = 0; b < 4; ++b)
            #pragma unroll
            for (int c = 0; c < 4; ++c) acc[a][b][c] = 0.0f;

    uint4 rah[2], ral[2], rbh[4], rbl[4];

    #pragma unroll
    for (int i = 0; i < 2; ++i) {
        int idx = tid + 256 * i, row = idx >> 3, kq = idx & 7;
        long off = (long)(m0 + row) * 4096 + kOff + kq * 8;
        rah[i] = *(const uint4*)(Ah + off);
        ral[i] = *(const uint4*)(Al + off);
    }
    #pragma unroll
    for (int i = 0; i < 4; ++i) {
        int idx = tid + 256 * i, row = idx >> 3, kq = idx & 7;
        long off = (long)(n0 + row) * 4096 + kOff + kq * 8;
        rbh[i] = *(const uint4*)(Bh + off);
        rbl[i] = *(const uint4*)(Bl + off);
    }
    #pragma unroll
    for (int i = 0; i < 2; ++i) {
        int idx = tid + 256 * i, row = idx >> 3, kq = idx & 7;
        uint32_t sw = row * 128 + ((kq * 16) ^ ((row & 7) << 4));
        *(uint4*)(dsm + sw)        = rah[i];
        *(uint4*)(dsm + 8192 + sw) = ral[i];
    }
    #pragma unroll
    for (int i = 0; i < 4; ++i) {
        int idx = tid + 256 * i, row = idx >> 3, kq = idx & 7;
        uint32_t sw = row * 128 + ((kq * 16) ^ ((row & 7) << 4));
        *(uint4*)(dsm + 16384 + sw) = rbh[i];
        *(uint4*)(dsm + 32768 + sw) = rbl[i];
    }
    __syncthreads();

    const int swz = laneR << 4;

    for (int kt = 0; kt < KT; ++kt) {
        if (kt + 1 < KT) {
            #pragma unroll
            for (int i = 0; i < 2; ++i) {
                int idx = tid + 256 * i, row = idx >> 3, kq = idx & 7;
                long off = (long)(m0 + row) * 4096 + kOff + (kt + 1) * 64 + kq * 8;
                rah[i] = *(const uint4*)(Ah + off);
                ral[i] = *(const uint4*)(Al + off);
            }
            #pragma unroll
            for (int i = 0; i < 4; ++i) {
                int idx = tid + 256 * i, row = idx >> 3, kq = idx & 7;
                long off = (long)(n0 + row) * 4096 + kOff + (kt + 1) * 64 + kq * 8;
                rbh[i] = *(const uint4*)(Bh + off);
                rbl[i] = *(const uint4*)(Bl + off);
            }
        }

        const char* st = dsm + (kt & 1) * STG;
        #pragma unroll
        for (int ks = 0; ks < 4; ++ks) {
            const int kb = ks * 32 + laneK4;
            const int k0x = kb ^ swz, k1x = (kb + 16) ^ swz;
            uint32_t fAh[2][4], fAl[2][4], fBh[4][2], fBl[4][2];
            #pragma unroll
            for (int mt = 0; mt < 2; ++mt) {
                const int r0 = (wm * 32 + mt * 16 + laneR) * 128;
                const int r1 = r0 + 8 * 128;
                fAh[mt][0] = lds32(st + r0 + k0x);
                fAh[mt][1] = lds32(st + r1 + k0x);
                fAh[mt][2] = lds32(st + r0 + k1x);
                fAh[mt][3] = lds32(st + r1 + k1x);
                fAl[mt][0] = lds32(st + 8192 + r0 + k0x);
                fAl[mt][1] = lds32(st + 8192 + r1 + k0x);
                fAl[mt][2] = lds32(st + 8192 + r0 + k1x);
                fAl[mt][3] = lds32(st + 8192 + r1 + k1x);
            }
            #pragma unroll
            for (int nt = 0; nt < 4; ++nt) {
                const int rb = (wn * 32 + nt * 8 + laneR) * 128;
                fBh[nt][0] = lds32(st + 16384 + rb + k0x);
                fBh[nt][1] = lds32(st + 16384 + rb + k1x);
                fBl[nt][0] = lds32(st + 32768 + rb + k0x);
                fBl[nt][1] = lds32(st + 32768 + rb + k1x);
            }
            #pragma unroll
            for (int mt = 0; mt < 2; ++mt)
                #pragma unroll
                for (int nt = 0; nt < 4; ++nt) {
                    mma16816(acc[mt][nt], fAh[mt], fBh[nt]);
                    mma16816(acc[mt][nt], fAh[mt], fBl[nt]);
                    mma16816(acc[mt][nt], fAl[mt], fBh[nt]);
                }
        }

        if (kt + 1 < KT) {
            char* nx = dsm + ((kt + 1) & 1) * STG;
            #pragma unroll
            for (int i = 0; i < 2; ++i) {
                int idx = tid + 256 * i, row = idx >> 3, kq = idx & 7;
                uint32_t sw = row * 128 + ((kq * 16) ^ ((row & 7) << 4));
                *(uint4*)(nx + sw)        = rah[i];
                *(uint4*)(nx + 8192 + sw) = ral[i];
            }
            #pragma unroll
            for (int i = 0; i < 4; ++i) {
                int idx = tid + 256 * i, row = idx >> 3, kq = idx & 7;
                uint32_t sw = row * 128 + ((kq * 16) ^ ((row & 7) << 4));
                *(uint4*)(nx + 16384 + sw) = rbh[i];
                *(uint4*)(nx + 32768 + sw) = rbl[i];
            }
            __syncthreads();
        }
    }

    #pragma unroll
    for (int mt = 0; mt < 2; ++mt)
        #pragma unroll
        for (int nt = 0; nt < 4; ++nt) {
            const int r0 = m0 + wm * 32 + mt * 16 + laneR;
            const int nc = n0 + wn * 32 + nt * 8 + 2 * (lane & 3);
            if (TANH) {
                const float b0 = bias[nc], b1 = bias[nc + 1];
                float v00 = tanhf(acc[mt][nt][0] + b0);
                float v01 = tanhf(acc[mt][nt][1] + b1);
                float v10 = tanhf(acc[mt][nt][2] + b0);
                float v11 = tanhf(acc[mt][nt][3] + b1);
                bf16 h00, l00, h01, l01, h10, l10, h11, l11;
                split_bf16(v00, h00, l00); split_bf16(v01, h01, l01);
                split_bf16(v10, h10, l10); split_bf16(v11, h11, l11);
                *(__nv_bfloat162*)(oH + (long)r0 * 4096 + nc)       = __halves2bfloat162(h00, h01);
                *(__nv_bfloat162*)(oH + (long)(r0 + 8) * 4096 + nc) = __halves2bfloat162(h10, h11);
                *(__nv_bfloat162*)(oL + (long)r0 * 4096 + nc)       = __halves2bfloat162(l00, l01);
                *(__nv_bfloat162*)(oL + (long)(r0 + 8) * 4096 + nc) = __halves2bfloat162(l10, l11);
            } else {
                float* P = oP + (long)blockIdx.z * 65536;
                *(float2*)(P + (long)r0 * 256 + nc)       = make_float2(acc[mt][nt][0], acc[mt][nt][1]);
                *(float2*)(P + (long)(r0 + 8) * 256 + nc) = make_float2(acc[mt][nt][2], acc[mt][nt][3]);
            }
        }
}

// ---------------- reduce: split-K partials + bias -> pts + out tail ----------------
__global__ void reduce_pts(const float* __restrict__ P, const float* __restrict__ b3,
                           float* __restrict__ pts, float* __restrict__ otail)
{
    const int i = blockIdx.x * 256 + threadIdx.x;
    const int m = i >> 8, n = i & 255;
    if (n >= 200) return;
    float s = b3[n];
    #pragma unroll
    for (int zz = 0; zz < 16; ++zz) s += P[zz * 65536 + i];
    pts[m * 200 + n] = s;
    otail[m * 200 + n] = s;
}

// ---------------- launch ----------------
extern "C" void kernel_launch(void* const* d_in, const int* in_sizes, int n_in,
                              void* d_out, int out_size)
{
    const float* x   = (const float*)d_in[0];
    const float* V   = (const float*)d_in[2];
    const float* lin = (const float*)d_in[3];
    const float* W1  = (const float*)d_in[4];
    const float* b1  = (const float*)d_in[5];
    const float* W2  = (const float*)d_in[6];
    const float* b2  = (const float*)d_in[7];
    const float* W3  = (const float*)d_in[8];
    const float* b3  = (const float*)d_in[9];
    float* out = (float*)d_out;

    bf16 *Ah, *Al, *Ah2, *Al2, *Ah3, *Al3, *W1h, *W1l, *W2h, *W2l, *W3h, *W3l;
    float *p3, *pts;
    cudaGetSymbolAddress((void**)&Ah,  g_Ah);
    cudaGetSymbolAddress((void**)&Al,  g_Al);
    cudaGetSymbolAddress((void**)&Ah2, g_Ah2);
    cudaGetSymbolAddress((void**)&Al2, g_Al2);
    cudaGetSymbolAddress((void**)&Ah3, g_Ah3);
    cudaGetSymbolAddress((void**)&Al3, g_Al3);
    cudaGetSymbolAddress((void**)&W1h, g_W1h);
    cudaGetSymbolAddress((void**)&W1l, g_W1l);
    cudaGetSymbolAddress((void**)&W2h, g_W2h);
    cudaGetSymbolAddress((void**)&W2l, g_W2l);
    cudaGetSymbolAddress((void**)&W3h, g_W3h);
    cudaGetSymbolAddress((void**)&W3l, g_W3l);
    cudaGetSymbolAddress((void**)&p3,  g_p3);
    cudaGetSymbolAddress((void**)&pts, g_pts);

    const int prep_sm = (int)PREP_SMEM;
    cudaFuncSetAttribute(prep_all,  cudaFuncAttributeMaxDynamicSharedMemorySize, prep_sm);
    cudaFuncSetAttribute(ect_final, cudaFuncAttributeMaxDynamicSharedMemorySize, prep_sm);
    cudaFuncSetAttribute(gemm_mma<64, true>,  cudaFuncAttributeMaxDynamicSharedMemorySize, GMEM_SM);
    cudaFuncSetAttribute(gemm_mma<4, false>,  cudaFuncAttributeMaxDynamicSharedMemorySize, GMEM_SM);

    prep_all<<<8704, 256, prep_sm>>>(x, V, lin, W1, W2, W3,
                                     W1h, W1l, W2h, W2l, W3h, W3l, Ah, Al);

    gemm_mma<64, true><<<dim3(4, 32), 256, GMEM_SM>>>(Ah,  Al,  W1h, W1l, b1, Ah2, Al2, nullptr);
    gemm_mma<64, true><<<dim3(4, 32), 256, GMEM_SM>>>(Ah2, Al2, W2h, W2l, b2, Ah3, Al3, nullptr);
    gemm_mma<4, false><<<dim3(4, 2, 16), 256, GMEM_SM>>>(Ah3, Al3, W3h, W3l, nullptr, nullptr, nullptr, p3);

    reduce_pts<<<256, 256>>>(p3, b3, pts, out + 256 * 64 * 64);
    ect_final<<<256, 256, prep_sm>>>(pts, V, lin, out);
}

// round 6
// speedup vs baseline: 2.2965x; 1.1639x over previous
#include <cuda_runtime.h>
#include <cuda_bf16.h>
#include <cstdint>

typedef __nv_bfloat16 bf16;

// ---------------- scratch ----------------
__device__ bf16 g_Ah [256 * 4096], g_Al [256 * 4096];
__device__ bf16 g_Ah2[256 * 4096], g_Al2[256 * 4096];
__device__ bf16 g_Ah3[256 * 4096], g_Al3[256 * 4096];
__device__ bf16 g_W1h[4096u * 4096u], g_W1l[4096u * 4096u];
__device__ bf16 g_W2h[4096u * 4096u], g_W2l[4096u * 4096u];
__device__ bf16 g_W3h[256 * 4096],   g_W3l[256 * 4096];
__device__ float g_p3 [16 * 256 * 256];
__device__ float g_pts[256 * 200];

// ---------------- helpers ----------------
__device__ __forceinline__ float sig_apx(float a) {
    float r; asm("tanh.approx.f32 %0,%1;" : "=f"(r) : "f"(a * 0.5f));
    return fmaf(0.5f, r, 0.5f);
}
__device__ __forceinline__ void split_bf16(float v, bf16& h, bf16& l) {
    h = __float2bfloat16(v);
    l = __float2bfloat16(v - __bfloat162float(h));
}
__device__ __forceinline__ void mma16816(float* c, const uint32_t* a, const uint32_t* b) {
    asm volatile("mma.sync.aligned.m16n8k16.row.col.f32.bf16.bf16.f32 "
        "{%0,%1,%2,%3}, {%4,%5,%6,%7}, {%8,%9}, {%0,%1,%2,%3};"
        : "+f"(c[0]), "+f"(c[1]), "+f"(c[2]), "+f"(c[3])
        : "r"(a[0]), "r"(a[1]), "r"(a[2]), "r"(a[3]), "r"(b[0]), "r"(b[1]));
}
__device__ __forceinline__ void ldsm4(uint32_t* r, uint32_t addr) {
    asm volatile("ldmatrix.sync.aligned.m8n8.x4.shared.b16 {%0,%1,%2,%3}, [%4];"
        : "=r"(r[0]), "=r"(r[1]), "=r"(r[2]), "=r"(r[3]) : "r"(addr));
}
__device__ __forceinline__ void cpasync16(uint32_t dst, const void* src) {
    asm volatile("cp.async.cg.shared.global [%0], [%1], 16;" :: "r"(dst), "l"(src) : "memory");
}
__device__ __forceinline__ void cpcommit() {
    asm volatile("cp.async.commit_group;" ::: "memory");
}
template<int N> __device__ __forceinline__ void cpwait() {
    asm volatile("cp.async.wait_group %0;" :: "n"(N) : "memory");
}

// ---------------- ECT body (256 threads) ----------------
struct EctSm {
    float xs[200];
    float Vs[128];
    float lins[64];
    float e2[2][4096];
    unsigned char cnt2[2][4096];
    float red[256];
};
#define PREP_SMEM (sizeof(EctSm))

__device__ void ect_body(int g, int tid, const float* __restrict__ pts,
                         const float* __restrict__ V, const float* __restrict__ lin,
                         float* __restrict__ outf, bf16* __restrict__ outh,
                         bf16* __restrict__ outl, char* sm)
{
    EctSm& S = *reinterpret_cast<EctSm*>(sm);
    if (tid < 64)  S.lins[tid] = lin[tid];
    if (tid < 128) S.Vs[tid] = V[tid];
    if (tid < 100) {
        float2 p = reinterpret_cast<const float2*>(pts)[g * 100 + tid];
        S.xs[2 * tid] = p.x; S.xs[2 * tid + 1] = p.y;
    }
    for (int i = tid; i < 8192; i += 256) (&S.e2[0][0])[i] = 0.0f;
    for (int i = tid; i < 2048; i += 256) reinterpret_cast<int*>(S.cnt2)[i] = 0;
    __syncthreads();

    if (tid < 128) {
        const int t = tid & 63, half = tid >> 6;
        const float vx = S.Vs[t], vy = S.Vs[64 + t];
        float* e = &S.e2[half][t];
        unsigned char* cc = &S.cnt2[half][t];
        const int nbeg = half * 50;
        for (int n = 0; n < 50; ++n) {
            const float x0 = S.xs[2 * (nbeg + n)], x1 = S.xs[2 * (nbeg + n) + 1];
            const float nh = fmaf(x0, vx, x1 * vy);
            const int kf = __float2int_rd((nh + 1.0f) * 31.5f);
            if (kf >= 0 && kf < 64)         e[kf * 64]       += sig_apx(500.0f * (S.lins[kf] - nh));
            if (kf + 1 >= 0 && kf + 1 < 64) e[(kf + 1) * 64] += sig_apx(500.0f * (S.lins[kf + 1] - nh));
            int s = kf + 2; if (s < 0) s = 0;
            if (s < 64) cc[s * 64] = (unsigned char)(cc[s * 64] + 1);
        }
    }
    __syncthreads();

    if (tid < 64) {
        float run = 0.0f;
        for (int k = 0; k < 64; ++k) {
            const int o = k * 64 + tid;
            run += (float)(S.cnt2[0][o] + S.cnt2[1][o]);
            S.e2[0][o] = S.e2[0][o] + S.e2[1][o] + run;
        }
    }
    __syncthreads();

    float mx = 0.0f;
    for (int i = tid; i < 4096; i += 256) mx = fmaxf(mx, S.e2[0][i]);
    S.red[tid] = mx; __syncthreads();
    for (int off = 128; off > 0; off >>= 1) {
        if (tid < off) S.red[tid] = fmaxf(S.red[tid], S.red[tid + off]);
        __syncthreads();
    }
    const float inv = 1.0f / S.red[0];
    for (int i = tid; i < 4096; i += 256) {
        float v = S.e2[0][i] * inv;
        if (outf) outf[(long)g * 4096 + i] = v;
        if (outh) {
            bf16 h, l; split_bf16(v, h, l);
            outh[(long)g * 4096 + i] = h;
            outl[(long)g * 4096 + i] = l;
        }
    }
}

// ---------------- transpose body: W[k][n] -> T[n][k] hi/lo bf16, 64x64 tile ----------------
__device__ void transpose_body(int kt, int ntile, int tid, const float* __restrict__ W,
                               int Wn, bf16* __restrict__ Th, bf16* __restrict__ Tl, char* sm)
{
    float (*s)[65] = reinterpret_cast<float(*)[65]>(sm);
    const int k0 = kt * 64, n0 = ntile * 64;
    const int r = tid >> 4, c4 = (tid & 15) * 4;
    #pragma unroll
    for (int p = 0; p < 4; ++p) {
        const int kk = p * 16 + r;
        float4 v;
        if (Wn == 4096) {
            v = *reinterpret_cast<const float4*>(W + (long)(k0 + kk) * 4096 + n0 + c4);
        } else {
            float t0 = 0, t1 = 0, t2 = 0, t3 = 0;
            const long base = (long)(k0 + kk) * 200;
            if (n0 + c4 + 0 < 200) t0 = W[base + n0 + c4 + 0];
            if (n0 + c4 + 1 < 200) t1 = W[base + n0 + c4 + 1];
            if (n0 + c4 + 2 < 200) t2 = W[base + n0 + c4 + 2];
            if (n0 + c4 + 3 < 200) t3 = W[base + n0 + c4 + 3];
            v = make_float4(t0, t1, t2, t3);
        }
        s[kk][c4] = v.x; s[kk][c4 + 1] = v.y; s[kk][c4 + 2] = v.z; s[kk][c4 + 3] = v.w;
    }
    __syncthreads();
    #pragma unroll
    for (int q = 0; q < 2; ++q) {
        const int idx = tid + 256 * q;
        const int n = idx >> 3, kg = idx & 7;
        uint4 uh, ul;
        __nv_bfloat162* ph = reinterpret_cast<__nv_bfloat162*>(&uh);
        __nv_bfloat162* pl = reinterpret_cast<__nv_bfloat162*>(&ul);
        #pragma unroll
        for (int j = 0; j < 4; ++j) {
            bf16 h0, l0, h1, l1;
            split_bf16(s[kg * 8 + 2 * j][n],     h0, l0);
            split_bf16(s[kg * 8 + 2 * j + 1][n], h1, l1);
            ph[j] = __halves2bfloat162(h0, h1);
            pl[j] = __halves2bfloat162(l0, l1);
        }
        const long o = (long)(n0 + n) * 4096 + k0 + kg * 8;
        *reinterpret_cast<uint4*>(Th + o) = uh;
        *reinterpret_cast<uint4*>(Tl + o) = ul;
    }
}

// ---------------- fused prep ----------------
__global__ void __launch_bounds__(256) prep_all(const float* __restrict__ x,
    const float* __restrict__ V, const float* __restrict__ lin,
    const float* __restrict__ W1, const float* __restrict__ W2, const float* __restrict__ W3,
    bf16* W1h, bf16* W1l, bf16* W2h, bf16* W2l, bf16* W3h, bf16* W3l,
    bf16* Ah, bf16* Al)
{
    extern __shared__ char sm[];
    int b = blockIdx.x;
    const int tid = threadIdx.x;
    if (b < 4096)       transpose_body(b & 63, b >> 6, tid, W1, 4096, W1h, W1l, sm);
    else if (b < 8192) { b -= 4096; transpose_body(b & 63, b >> 6, tid, W2, 4096, W2h, W2l, sm); }
    else if (b < 8448) { b -= 8192; transpose_body(b & 63, b >> 6, tid, W3,  200, W3h, W3l, sm); }
    else                ect_body(b - 8448, tid, x, V, lin, nullptr, Ah, Al, sm);
}

__global__ void __launch_bounds__(256) ect_final(const float* __restrict__ pts,
    const float* __restrict__ V, const float* __restrict__ lin, float* __restrict__ out)
{
    extern __shared__ char sm[];
    ect_body(blockIdx.x, threadIdx.x, pts, V, lin, out, nullptr, nullptr, sm);
}

// ---------------- HMMA GEMM, cp.async + ldmatrix, bf16 hi/lo 3-product ----------------
// CTA 64x128, BK=64, 8 warps (2x4), warp 32x32, SW(16B-xor) smem, 2-stage cp.async.
#define STG 49152
#define GMEM_SM (2 * STG)

template<int KT, bool TANH>
__global__ void __launch_bounds__(256, 2) gemm_mma(const bf16* __restrict__ Ah,
                                                   const bf16* __restrict__ Al,
                                                   const bf16* __restrict__ Bh,
                                                   const bf16* __restrict__ Bl,
                                                   const float* __restrict__ bias,
                                                   bf16* __restrict__ oH,
                                                   bf16* __restrict__ oL,
                                                   float* __restrict__ oP)
{
    extern __shared__ __align__(16) char dsm[];
    const uint32_t smem0 = (uint32_t)__cvta_generic_to_shared(dsm);
    const int tid = threadIdx.x;
    const int lane = tid & 31, wid = tid >> 5;
    const int wm = wid >> 2, wn = wid & 3;
    const int m0 = blockIdx.x * 64, n0 = blockIdx.y * 128;
    const long kOff = TANH ? 0 : (long)blockIdx.z * (KT * 64);

    // cp.async addressing: thread handles rows r0+32i, fixed kq
    const int r0 = tid >> 3, kq = tid & 7;
    const uint32_t dsw = (uint32_t)(r0 * 128 + ((kq * 16) ^ ((r0 & 7) << 4)));
    const bf16* pAh = Ah + (long)(m0 + r0) * 4096 + kOff + kq * 8;
    const bf16* pAl = Al + (long)(m0 + r0) * 4096 + kOff + kq * 8;
    const bf16* pBh = Bh + (long)(n0 + r0) * 4096 + kOff + kq * 8;
    const bf16* pBl = Bl + (long)(n0 + r0) * 4096 + kOff + kq * 8;

    float acc[2][4][4];
    #pragma unroll
    for (int a = 0; a < 2; ++a)
        #pragma unroll
        for (int b = 0; b < 4; ++b)
            #pragma unroll
            for (int c = 0; c < 4; ++c) acc[a][b][c] = 0.0f;

    // ldmatrix addressing
    const int lr = lane & 7, lt = lane >> 3;
    const uint32_t aRow = (uint32_t)((wm * 32 + ((lt & 1) << 3) + lr) * 128);
    const int aK = (lt >> 1) * 16;
    const uint32_t bRow = (uint32_t)((wn * 32 + ((lt >> 1) << 3) + lr) * 128);
    const int bK = (lt & 1) * 16;
    const int sw = lr << 4;

    // prologue: stage 0
    {
        const uint32_t st = smem0;
        #pragma unroll
        for (int i = 0; i < 2; ++i) {
            cpasync16(st + dsw + i * 32 * 128,        pAh + (long)i * 32 * 4096);
            cpasync16(st + 8192 + dsw + i * 32 * 128, pAl + (long)i * 32 * 4096);
        }
        #pragma unroll
        for (int i = 0; i < 4; ++i) {
            cpasync16(st + 16384 + dsw + i * 32 * 128, pBh + (long)i * 32 * 4096);
            cpasync16(st + 32768 + dsw + i * 32 * 128, pBl + (long)i * 32 * 4096);
        }
        cpcommit();
    }

    for (int kt = 0; kt < KT; ++kt) {
        if (kt + 1 < KT) {
            const uint32_t st = smem0 + ((kt + 1) & 1) * STG;
            const long g = (long)(kt + 1) * 64;
            #pragma unroll
            for (int i = 0; i < 2; ++i) {
                cpasync16(st + dsw + i * 32 * 128,        pAh + g + (long)i * 32 * 4096);
                cpasync16(st + 8192 + dsw + i * 32 * 128, pAl + g + (long)i * 32 * 4096);
            }
            #pragma unroll
            for (int i = 0; i < 4; ++i) {
                cpasync16(st + 16384 + dsw + i * 32 * 128, pBh + g + (long)i * 32 * 4096);
                cpasync16(st + 32768 + dsw + i * 32 * 128, pBl + g + (long)i * 32 * 4096);
            }
            cpcommit();
            cpwait<1>();
        } else {
            cpwait<0>();
        }
        __syncthreads();

        const uint32_t st = smem0 + (kt & 1) * STG;
        #pragma unroll
        for (int ks = 0; ks < 4; ++ks) {
            const int ka = (ks * 32 + aK) ^ sw;
            const int kb = (ks * 32 + bK) ^ sw;
            uint32_t fAh[2][4], fAl[2][4], fBh[2][4], fBl[2][4];
            ldsm4(fAh[0], st + aRow + ka);
            ldsm4(fAh[1], st + aRow + 16 * 128 + ka);
            ldsm4(fAl[0], st + 8192 + aRow + ka);
            ldsm4(fAl[1], st + 8192 + aRow + 16 * 128 + ka);
            ldsm4(fBh[0], st + 16384 + bRow + kb);
            ldsm4(fBh[1], st + 16384 + bRow + 16 * 128 + kb);
            ldsm4(fBl[0], st + 32768 + bRow + kb);
            ldsm4(fBl[1], st + 32768 + bRow + 16 * 128 + kb);
            #pragma unroll
            for (int mt = 0; mt < 2; ++mt)
                #pragma unroll
                for (int nt = 0; nt < 4; ++nt) {
                    const uint32_t* bh = &fBh[nt >> 1][(nt & 1) * 2];
                    const uint32_t* bl = &fBl[nt >> 1][(nt & 1) * 2];
                    mma16816(acc[mt][nt], fAh[mt], bh);
                    mma16816(acc[mt][nt], fAh[mt], bl);
                    mma16816(acc[mt][nt], fAl[mt], bh);
                }
        }
        if (kt + 1 < KT) __syncthreads();
    }

    const int laneR = lane >> 2;
    #pragma unroll
    for (int mt = 0; mt < 2; ++mt)
        #pragma unroll
        for (int nt = 0; nt < 4; ++nt) {
            const int rr = m0 + wm * 32 + mt * 16 + laneR;
            const int nc = n0 + wn * 32 + nt * 8 + 2 * (lane & 3);
            if (TANH) {
                const float b0 = bias[nc], b1 = bias[nc + 1];
                float v00 = tanhf(acc[mt][nt][0] + b0);
                float v01 = tanhf(acc[mt][nt][1] + b1);
                float v10 = tanhf(acc[mt][nt][2] + b0);
                float v11 = tanhf(acc[mt][nt][3] + b1);
                bf16 h00, l00, h01, l01, h10, l10, h11, l11;
                split_bf16(v00, h00, l00); split_bf16(v01, h01, l01);
                split_bf16(v10, h10, l10); split_bf16(v11, h11, l11);
                *(__nv_bfloat162*)(oH + (long)rr * 4096 + nc)       = __halves2bfloat162(h00, h01);
                *(__nv_bfloat162*)(oH + (long)(rr + 8) * 4096 + nc) = __halves2bfloat162(h10, h11);
                *(__nv_bfloat162*)(oL + (long)rr * 4096 + nc)       = __halves2bfloat162(l00, l01);
                *(__nv_bfloat162*)(oL + (long)(rr + 8) * 4096 + nc) = __halves2bfloat162(l10, l11);
            } else {
                float* P = oP + (long)blockIdx.z * 65536;
                *(float2*)(P + (long)rr * 256 + nc)       = make_float2(acc[mt][nt][0], acc[mt][nt][1]);
                *(float2*)(P + (long)(rr + 8) * 256 + nc) = make_float2(acc[mt][nt][2], acc[mt][nt][3]);
            }
        }
}

// ---------------- reduce ----------------
__global__ void reduce_pts(const float* __restrict__ P, const float* __restrict__ b3,
                           float* __restrict__ pts, float* __restrict__ otail)
{
    const int i = blockIdx.x * 256 + threadIdx.x;
    const int m = i >> 8, n = i & 255;
    if (n >= 200) return;
    float s = b3[n];
    #pragma unroll
    for (int zz = 0; zz < 16; ++zz) s += P[zz * 65536 + i];
    pts[m * 200 + n] = s;
    otail[m * 200 + n] = s;
}

// ---------------- launch ----------------
extern "C" void kernel_launch(void* const* d_in, const int* in_sizes, int n_in,
                              void* d_out, int out_size)
{
    const float* x   = (const float*)d_in[0];
    const float* V   = (const float*)d_in[2];
    const float* lin = (const float*)d_in[3];
    const float* W1  = (const float*)d_in[4];
    const float* b1  = (const float*)d_in[5];
    const float* W2  = (const float*)d_in[6];
    const float* b2  = (const float*)d_in[7];
    const float* W3  = (const float*)d_in[8];
    const float* b3  = (const float*)d_in[9];
    float* out = (float*)d_out;

    bf16 *Ah, *Al, *Ah2, *Al2, *Ah3, *Al3, *W1h, *W1l, *W2h, *W2l, *W3h, *W3l;
    float *p3, *pts;
    cudaGetSymbolAddress((void**)&Ah,  g_Ah);
    cudaGetSymbolAddress((void**)&Al,  g_Al);
    cudaGetSymbolAddress((void**)&Ah2, g_Ah2);
    cudaGetSymbolAddress((void**)&Al2, g_Al2);
    cudaGetSymbolAddress((void**)&Ah3, g_Ah3);
    cudaGetSymbolAddress((void**)&Al3, g_Al3);
    cudaGetSymbolAddress((void**)&W1h, g_W1h);
    cudaGetSymbolAddress((void**)&W1l, g_W1l);
    cudaGetSymbolAddress((void**)&W2h, g_W2h);
    cudaGetSymbolAddress((void**)&W2l, g_W2l);
    cudaGetSymbolAddress((void**)&W3h, g_W3h);
    cudaGetSymbolAddress((void**)&W3l, g_W3l);
    cudaGetSymbolAddress((void**)&p3,  g_p3);
    cudaGetSymbolAddress((void**)&pts, g_pts);

    const int prep_sm = (int)PREP_SMEM;
    cudaFuncSetAttribute(prep_all,  cudaFuncAttributeMaxDynamicSharedMemorySize, prep_sm);
    cudaFuncSetAttribute(ect_final, cudaFuncAttributeMaxDynamicSharedMemorySize, prep_sm);
    cudaFuncSetAttribute(gemm_mma<64, true>,  cudaFuncAttributeMaxDynamicSharedMemorySize, GMEM_SM);
    cudaFuncSetAttribute(gemm_mma<4, false>,  cudaFuncAttributeMaxDynamicSharedMemorySize, GMEM_SM);

    prep_all<<<8704, 256, prep_sm>>>(x, V, lin, W1, W2, W3,
                                     W1h, W1l, W2h, W2l, W3h, W3l, Ah, Al);

    gemm_mma<64, true><<<dim3(4, 32), 256, GMEM_SM>>>(Ah,  Al,  W1h, W1l, b1, Ah2, Al2, nullptr);
    gemm_mma<64, true><<<dim3(4, 32), 256, GMEM_SM>>>(Ah2, Al2, W2h, W2l, b2, Ah3, Al3, nullptr);
    gemm_mma<4, false><<<dim3(4, 2, 16), 256, GMEM_SM>>>(Ah3, Al3, W3h, W3l, nullptr, nullptr, nullptr, p3);

    reduce_pts<<<256, 256>>>(p3, b3, pts, out + 256 * 64 * 64);
    ect_final<<<256, 256, prep_sm>>>(pts, V, lin, out);
}